// round 2
// baseline (speedup 1.0000x reference)
#include <cuda_runtime.h>
#include <math.h>

#define N_DIM 1024
#define K_DIM 1024
#define NELEM 33554432  // 4*8192*1024

// Scratch (device globals; no allocation allowed)
__device__ float g_K [NELEM];
__device__ float g_V [NELEM];
__device__ float g_Q [NELEM];
__device__ float g_KP[NELEM];
__device__ float g_QP[NELEM];
__device__ float g_R [NELEM];

__device__ __forceinline__ unsigned f2tf32(float f) {
    unsigned u;
    asm("cvt.rna.tf32.f32 %0, %1;" : "=r"(u) : "f"(f));
    return u;
}

__device__ __forceinline__ void mma_tf32(float c[4],
    unsigned a0, unsigned a1, unsigned a2, unsigned a3,
    unsigned b0, unsigned b1)
{
    asm volatile(
        "mma.sync.aligned.m16n8k8.row.col.f32.tf32.tf32.f32 "
        "{%0,%1,%2,%3}, {%4,%5,%6,%7}, {%8,%9}, {%0,%1,%2,%3};\n"
        : "+f"(c[0]), "+f"(c[1]), "+f"(c[2]), "+f"(c[3])
        : "r"(a0), "r"(a1), "r"(a2), "r"(a3), "r"(b0), "r"(b1));
}

#define AS_STR 36    // 36 % 32 == 4  -> conflict-free A fragment loads
#define BS_STR 136   // 136 % 32 == 8 -> conflict-free B fragment loads
#define SMEM_WORDS (2*128*AS_STR + 2*32*BS_STR)
#define SMEM_BYTES (SMEM_WORDS * 4)

// C[M,1024] = A[M,1024] @ W[1024,1024] (+bias) with fused epilogue.
// EPI 0: C = acc + bias
// EPI 1: C = tanh(acc + bias) * extra[n]      (extra = phase_scale)
// EPI 2: C = acc + bias + extra[m*1024 + n]   (extra = x residual)
template<int EPI>
__global__ void __launch_bounds__(256)
gemm_k(const float* __restrict__ A, const float* __restrict__ W,
       const float* __restrict__ bias, const float* __restrict__ extra,
       float* __restrict__ C)
{
    extern __shared__ unsigned sm[];
    unsigned* As = sm;                    // [2][128][AS_STR]
    unsigned* Bs = sm + 2*128*AS_STR;     // [2][32][BS_STR]

    const int tid  = threadIdx.x;
    const int lane = tid & 31;
    const int warp = tid >> 5;
    const int wm   = warp & 1;        // 2 warps along M (64 rows each)
    const int wn   = warp >> 1;       // 4 warps along N (32 cols each)
    const int gid  = lane >> 2;
    const int tg   = lane & 3;

    const long bm0 = (long)blockIdx.y * 128;
    const int  bn0 = blockIdx.x * 128;

    // per-thread global load pointers
    const float* aG = A + (bm0 + (tid >> 3)) * K_DIM + (tid & 7) * 4;
    const float* bG = W + (long)(tid >> 5) * N_DIM + bn0 + (tid & 31) * 4;

    float4 ar[4], br[4];

    auto g2r = [&](int kt) {
        #pragma unroll
        for (int i = 0; i < 4; i++)
            ar[i] = *(const float4*)(aG + (long)i * 32 * K_DIM + kt * 32);
        #pragma unroll
        for (int i = 0; i < 4; i++)
            br[i] = *(const float4*)(bG + (long)(kt * 32 + i * 8) * N_DIM);
    };

    auto r2s = [&](int buf) {
        unsigned* a = As + buf * 128 * AS_STR;
        unsigned* b = Bs + buf * 32 * BS_STR;
        #pragma unroll
        for (int i = 0; i < 4; i++) {
            int r = i * 32 + (tid >> 3);
            int c = (tid & 7) * 4;
            a[r * AS_STR + c + 0] = f2tf32(ar[i].x);
            a[r * AS_STR + c + 1] = f2tf32(ar[i].y);
            a[r * AS_STR + c + 2] = f2tf32(ar[i].z);
            a[r * AS_STR + c + 3] = f2tf32(ar[i].w);
        }
        #pragma unroll
        for (int i = 0; i < 4; i++) {
            int r = i * 8 + (tid >> 5);
            int c = (tid & 31) * 4;
            b[r * BS_STR + c + 0] = f2tf32(br[i].x);
            b[r * BS_STR + c + 1] = f2tf32(br[i].y);
            b[r * BS_STR + c + 2] = f2tf32(br[i].z);
            b[r * BS_STR + c + 3] = f2tf32(br[i].w);
        }
    };

    float acc[4][4][4];
    #pragma unroll
    for (int i = 0; i < 4; i++)
        #pragma unroll
        for (int j = 0; j < 4; j++)
            #pragma unroll
            for (int k = 0; k < 4; k++)
                acc[i][j][k] = 0.f;

    g2r(0);
    r2s(0);

    #pragma unroll 1
    for (int kt = 0; kt < 32; kt++) {
        __syncthreads();
        if (kt < 31) g2r(kt + 1);

        const unsigned* a_ = As + (kt & 1) * 128 * AS_STR;
        const unsigned* b_ = Bs + (kt & 1) * 32 * BS_STR;

        #pragma unroll
        for (int kk = 0; kk < 4; kk++) {
            unsigned af[4][4], bf[4][2];
            #pragma unroll
            for (int im = 0; im < 4; im++) {
                const unsigned* p = a_ + (wm * 64 + im * 16) * AS_STR + kk * 8;
                af[im][0] = p[gid * AS_STR + tg];
                af[im][1] = p[(gid + 8) * AS_STR + tg];
                af[im][2] = p[gid * AS_STR + tg + 4];
                af[im][3] = p[(gid + 8) * AS_STR + tg + 4];
            }
            #pragma unroll
            for (int in = 0; in < 4; in++) {
                const unsigned* p = b_ + (kk * 8 + tg) * BS_STR + wn * 32 + in * 8 + gid;
                bf[in][0] = p[0];
                bf[in][1] = p[4 * BS_STR];
            }
            #pragma unroll
            for (int im = 0; im < 4; im++)
                #pragma unroll
                for (int in = 0; in < 4; in++)
                    mma_tf32(acc[im][in],
                             af[im][0], af[im][1], af[im][2], af[im][3],
                             bf[in][0], bf[in][1]);
        }

        if (kt < 31) r2s((kt + 1) & 1);
    }

    // Epilogue
    #pragma unroll
    for (int im = 0; im < 4; im++) {
        #pragma unroll
        for (int in = 0; in < 4; in++) {
            int c0 = bn0 + wn * 32 + in * 8 + 2 * tg;
            #pragma unroll
            for (int h = 0; h < 2; h++) {
                long row = bm0 + wm * 64 + im * 16 + gid + h * 8;
                float v0 = acc[im][in][2 * h + 0] + bias[c0];
                float v1 = acc[im][in][2 * h + 1] + bias[c0 + 1];
                if (EPI == 1) {
                    v0 = tanhf(v0) * extra[c0];
                    v1 = tanhf(v1) * extra[c0 + 1];
                } else if (EPI == 2) {
                    v0 += extra[row * N_DIM + c0];
                    v1 += extra[row * N_DIM + c0 + 1];
                }
                *(float2*)(C + row * N_DIM + c0) = make_float2(v0, v1);
            }
        }
    }
}

// bound = V * exp(i*KP); per-chunk (64) cumulative sum; retrieve with QP; /sqrt(D)
__global__ void __launch_bounds__(256)
bind_scan_k(const float* __restrict__ V, const float* __restrict__ KP,
            const float* __restrict__ QP, float* __restrict__ R)
{
    const float inv = 0.03125f;  // 1/sqrt(1024)
    long idx = (long)blockIdx.x * 64 * 1024 + threadIdx.x * 4;
    float4 mr = make_float4(0.f, 0.f, 0.f, 0.f);
    float4 mi = make_float4(0.f, 0.f, 0.f, 0.f);

    #pragma unroll 4
    for (int s = 0; s < 64; s++, idx += 1024) {
        float4 v  = *(const float4*)(V + idx);
        float4 kp = *(const float4*)(KP + idx);
        float4 qp = *(const float4*)(QP + idx);
        float4 out;
        float sk, ck, sq, cq;

        __sincosf(kp.x, &sk, &ck);
        mr.x = fmaf(v.x, ck, mr.x); mi.x = fmaf(v.x, sk, mi.x);
        __sincosf(qp.x, &sq, &cq);
        out.x = (mr.x * cq + mi.x * sq) * inv;

        __sincosf(kp.y, &sk, &ck);
        mr.y = fmaf(v.y, ck, mr.y); mi.y = fmaf(v.y, sk, mi.y);
        __sincosf(qp.y, &sq, &cq);
        out.y = (mr.y * cq + mi.y * sq) * inv;

        __sincosf(kp.z, &sk, &ck);
        mr.z = fmaf(v.z, ck, mr.z); mi.z = fmaf(v.z, sk, mi.z);
        __sincosf(qp.z, &sq, &cq);
        out.z = (mr.z * cq + mi.z * sq) * inv;

        __sincosf(kp.w, &sk, &ck);
        mr.w = fmaf(v.w, ck, mr.w); mi.w = fmaf(v.w, sk, mi.w);
        __sincosf(qp.w, &sq, &cq);
        out.w = (mr.w * cq + mi.w * sq) * inv;

        *(float4*)(R + idx) = out;
    }
}

// In-place row LayerNorm over D=1024
__global__ void __launch_bounds__(256)
ln_k(float* __restrict__ R, const float* __restrict__ g, const float* __restrict__ b)
{
    long row = blockIdx.x;
    float4* p = (float4*)(R + row * 1024) + threadIdx.x;
    float4 v = *p;
    float s = v.x + v.y + v.z + v.w;
    float q = v.x * v.x + v.y * v.y + v.z * v.z + v.w * v.w;

    #pragma unroll
    for (int o = 16; o; o >>= 1) {
        s += __shfl_xor_sync(0xffffffffu, s, o);
        q += __shfl_xor_sync(0xffffffffu, q, o);
    }
    __shared__ float ss[8], sq2[8];
    int lane = threadIdx.x & 31, w = threadIdx.x >> 5;
    if (lane == 0) { ss[w] = s; sq2[w] = q; }
    __syncthreads();
    if (threadIdx.x == 0) {
        float S = 0.f, Q = 0.f;
        #pragma unroll
        for (int i = 0; i < 8; i++) { S += ss[i]; Q += sq2[i]; }
        ss[0] = S; sq2[0] = Q;
    }
    __syncthreads();
    float mu   = ss[0] * (1.f / 1024.f);
    float var  = sq2[0] * (1.f / 1024.f) - mu * mu;
    float rstd = rsqrtf(var + 1e-5f);

    int c = threadIdx.x * 4;
    float4 gg = *(const float4*)(g + c);
    float4 bb = *(const float4*)(b + c);
    v.x = (v.x - mu) * rstd * gg.x + bb.x;
    v.y = (v.y - mu) * rstd * gg.y + bb.y;
    v.z = (v.z - mu) * rstd * gg.z + bb.z;
    v.w = (v.w - mu) * rstd * gg.w + bb.w;
    *p = v;
}

extern "C" void kernel_launch(void* const* d_in, const int* in_sizes, int n_in,
                              void* d_out, int out_size)
{
    const float* x   = (const float*)d_in[0];
    const float* Wk  = (const float*)d_in[1];
    const float* bk  = (const float*)d_in[2];
    const float* Wv  = (const float*)d_in[3];
    const float* bv  = (const float*)d_in[4];
    const float* Wq  = (const float*)d_in[5];
    const float* bq  = (const float*)d_in[6];
    const float* Wkp = (const float*)d_in[7];
    const float* bkp = (const float*)d_in[8];
    const float* Wqp = (const float*)d_in[9];
    const float* bqp = (const float*)d_in[10];
    const float* ps  = (const float*)d_in[11];
    const float* lng = (const float*)d_in[12];
    const float* lnb = (const float*)d_in[13];
    const float* Wo  = (const float*)d_in[14];
    const float* bo  = (const float*)d_in[15];
    float* out = (float*)d_out;

    const int M = in_sizes[0] / 1024;  // 32768

    float *pK, *pV, *pQ, *pKP, *pQP, *pR;
    cudaGetSymbolAddress((void**)&pK,  g_K);
    cudaGetSymbolAddress((void**)&pV,  g_V);
    cudaGetSymbolAddress((void**)&pQ,  g_Q);
    cudaGetSymbolAddress((void**)&pKP, g_KP);
    cudaGetSymbolAddress((void**)&pQP, g_QP);
    cudaGetSymbolAddress((void**)&pR,  g_R);

    cudaFuncSetAttribute(gemm_k<0>, cudaFuncAttributeMaxDynamicSharedMemorySize, SMEM_BYTES);
    cudaFuncSetAttribute(gemm_k<1>, cudaFuncAttributeMaxDynamicSharedMemorySize, SMEM_BYTES);
    cudaFuncSetAttribute(gemm_k<2>, cudaFuncAttributeMaxDynamicSharedMemorySize, SMEM_BYTES);

    dim3 grid(N_DIM / 128, M / 128), blk(256);

    gemm_k<0><<<grid, blk, SMEM_BYTES>>>(x, Wk, bk, nullptr, pK);
    gemm_k<0><<<grid, blk, SMEM_BYTES>>>(x, Wv, bv, nullptr, pV);
    gemm_k<0><<<grid, blk, SMEM_BYTES>>>(x, Wq, bq, nullptr, pQ);
    gemm_k<1><<<grid, blk, SMEM_BYTES>>>(pK, Wkp, bkp, ps, pKP);
    gemm_k<1><<<grid, blk, SMEM_BYTES>>>(pQ, Wqp, bqp, ps, pQP);
    bind_scan_k<<<M / 64, 256>>>(pV, pKP, pQP, pR);
    ln_k<<<M, 256>>>(pR, lng, lnb);
    gemm_k<2><<<grid, blk, SMEM_BYTES>>>(pR, Wo, bo, x, out);
}

// round 4
// speedup vs baseline: 1.3183x; 1.3183x over previous
#include <cuda_runtime.h>
#include <cstdint>
#include <math.h>

#define N_DIM 1024
#define K_DIM 1024
#define NELEM 33554432  // 4*8192*1024

#define MT 128
#define NT 128
#define KT 32
#define STAGES 3
#define STAGE_BYTES 32768                 // A 16KB + B 16KB
#define SMEM_TOTAL (STAGES * STAGE_BYTES) // 96KB

// Scratch (device globals; no allocation allowed)
__device__ float g_K [NELEM];
__device__ float g_V [NELEM];
__device__ float g_Q [NELEM];
__device__ float g_KP[NELEM];
__device__ float g_QP[NELEM];
__device__ float g_R [NELEM];
__device__ float g_X [NELEM];
__device__ float g_WT[6 * 1024 * 1024];

// ---------------- helpers ----------------
__device__ __forceinline__ unsigned f2tf32(float f) {
    unsigned u;
    asm("cvt.rna.tf32.f32 %0, %1;" : "=r"(u) : "f"(f));
    return u;
}
__device__ __forceinline__ float rnd32(float f) { return __uint_as_float(f2tf32(f)); }

__device__ __forceinline__ uint32_t smem_u32(const void* p) {
    uint32_t a;
    asm("{ .reg .u64 t; cvta.to.shared.u64 t, %1; cvt.u32.u64 %0, t; }" : "=r"(a) : "l"(p));
    return a;
}
__device__ __forceinline__ void cp16(uint32_t dst, const void* src) {
    asm volatile("cp.async.cg.shared.global [%0], [%1], 16;\n" :: "r"(dst), "l"(src) : "memory");
}
__device__ __forceinline__ void cp_commit() {
    asm volatile("cp.async.commit_group;\n" ::: "memory");
}
template <int N> __device__ __forceinline__ void cp_wait() {
    asm volatile("cp.async.wait_group %0;\n" :: "n"(N) : "memory");
}
__device__ __forceinline__ void ldmx4(uint32_t& r0, uint32_t& r1, uint32_t& r2, uint32_t& r3,
                                      uint32_t addr) {
    asm volatile("ldmatrix.sync.aligned.m8n8.x4.shared.b16 {%0,%1,%2,%3}, [%4];"
                 : "=r"(r0), "=r"(r1), "=r"(r2), "=r"(r3) : "r"(addr));
}
__device__ __forceinline__ void mma_tf32(float c[4],
    uint32_t a0, uint32_t a1, uint32_t a2, uint32_t a3, uint32_t b0, uint32_t b1)
{
    asm volatile(
        "mma.sync.aligned.m16n8k8.row.col.f32.tf32.tf32.f32 "
        "{%0,%1,%2,%3}, {%4,%5,%6,%7}, {%8,%9}, {%0,%1,%2,%3};\n"
        : "+f"(c[0]), "+f"(c[1]), "+f"(c[2]), "+f"(c[3])
        : "r"(a0), "r"(a1), "r"(a2), "r"(a3), "r"(b0), "r"(b1));
}

// ---------------- GEMM ----------------
// C[M,1024] = A[M,1024] @ WT^T.  A and WT must already be tf32-rounded.
// WT is [N rows, K cols] (i.e. W transposed), row stride 1024.
// EPI 0: C = acc + bias                      (RND -> round result to tf32)
// EPI 1: C = tanh(acc + bias) * extra[n]
// EPI 2: C = acc + bias + extra[row*1024+n]
template <int EPI, int RND>
__global__ void __launch_bounds__(256, 2)
gemm_tc(const float* __restrict__ A, const float* __restrict__ WT,
        const float* __restrict__ bias, const float* __restrict__ extra,
        float* __restrict__ C)
{
    extern __shared__ char smem[];
    const uint32_t tileBase = smem_u32(smem);

    const int tid  = threadIdx.x;
    const int wid  = tid >> 5;
    const int lane = tid & 31;
    const int wm   = wid >> 1;        // 0..3 : 32-row strip
    const int wn   = wid & 1;         // 0..1 : 64-col strip
    const int g    = lane >> 2;
    const int tg   = lane & 3;

    const long bm0 = (long)blockIdx.y * MT;
    const int  bn0 = blockIdx.x * NT;

    const float* Abase = A  + bm0 * K_DIM;
    const float* Bbase = WT + (long)bn0 * K_DIM;

    // ldmatrix per-thread geometry (rows laid out 128B apart, 16B chunks
    // XOR-swizzled by row&7 -> conflict-free ldmatrix and cp.async)
    const uint32_t rsw   = lane & 7;
    const uint32_t aoff0 = (uint32_t)((wm * 32 + ((lane >> 3) & 1) * 8 + (lane & 7)) * 128);
    const uint32_t hbitA = (lane >> 4) & 1;
    const uint32_t boff0 = (uint32_t)((wn * 64 + ((lane >> 4) & 1) * 8 + (lane & 7)) * 128) + 16384u;
    const uint32_t hbitB = (lane >> 3) & 1;

    auto fill = [&](int s) {
        const uint32_t buf = tileBase + (uint32_t)(s % STAGES) * STAGE_BYTES;
        const int k0 = s * KT;
        #pragma unroll
        for (int i = 0; i < 4; i++) {          // A: 128 rows x 8 chunks
            int o = tid + 256 * i;
            int row = o >> 3, c = o & 7;
            cp16(buf + (uint32_t)(row * 128 + ((c ^ (row & 7)) << 4)),
                 Abase + row * K_DIM + k0 + c * 4);
        }
        #pragma unroll
        for (int i = 0; i < 4; i++) {          // B: 128 rows x 8 chunks
            int o = tid + 256 * i;
            int row = o >> 3, c = o & 7;
            cp16(buf + 16384u + (uint32_t)(row * 128 + ((c ^ (row & 7)) << 4)),
                 Bbase + row * K_DIM + k0 + c * 4);
        }
        cp_commit();
    };

    float acc[2][8][4];
    #pragma unroll
    for (int i = 0; i < 2; i++)
        #pragma unroll
        for (int j = 0; j < 8; j++)
            #pragma unroll
            for (int k = 0; k < 4; k++)
                acc[i][j][k] = 0.f;

    fill(0);
    fill(1);

    #pragma unroll 1
    for (int kt = 0; kt < 32; kt++) {
        if (kt < 31) cp_wait<1>(); else cp_wait<0>();
        __syncthreads();
        if (kt < 30) fill(kt + 2);

        const uint32_t sbase = tileBase + (uint32_t)(kt % STAGES) * STAGE_BYTES;
        #pragma unroll
        for (int kk = 0; kk < 4; kk++) {
            uint32_t af[2][4], bf[8][2];
            const uint32_t cA = ((uint32_t)(kk * 2) + hbitA) ^ rsw;
            const uint32_t cB = ((uint32_t)(kk * 2) + hbitB) ^ rsw;
            ldmx4(af[0][0], af[0][1], af[0][2], af[0][3], sbase + aoff0 + (cA << 4));
            ldmx4(af[1][0], af[1][1], af[1][2], af[1][3], sbase + aoff0 + 2048u + (cA << 4));
            #pragma unroll
            for (int q = 0; q < 4; q++)
                ldmx4(bf[2 * q][0], bf[2 * q][1], bf[2 * q + 1][0], bf[2 * q + 1][1],
                      sbase + boff0 + (uint32_t)(q * 2048) + (cB << 4));
            #pragma unroll
            for (int im = 0; im < 2; im++)
                #pragma unroll
                for (int in = 0; in < 8; in++)
                    mma_tf32(acc[im][in],
                             af[im][0], af[im][1], af[im][2], af[im][3],
                             bf[in][0], bf[in][1]);
        }
    }

    // Epilogue
    #pragma unroll
    for (int im = 0; im < 2; im++) {
        #pragma unroll
        for (int in = 0; in < 8; in++) {
            const int col = bn0 + wn * 64 + in * 8 + 2 * tg;
            const float b0 = __ldg(bias + col);
            const float b1 = __ldg(bias + col + 1);
            #pragma unroll
            for (int h = 0; h < 2; h++) {
                const long row = bm0 + wm * 32 + im * 16 + g + h * 8;
                float v0 = acc[im][in][2 * h + 0] + b0;
                float v1 = acc[im][in][2 * h + 1] + b1;
                if (EPI == 1) {
                    v0 = tanhf(v0) * __ldg(extra + col);
                    v1 = tanhf(v1) * __ldg(extra + col + 1);
                } else if (EPI == 2) {
                    v0 += extra[row * N_DIM + col];
                    v1 += extra[row * N_DIM + col + 1];
                }
                if (RND) { v0 = rnd32(v0); v1 = rnd32(v1); }
                *(float2*)(C + row * N_DIM + col) = make_float2(v0, v1);
            }
        }
    }
}

// ---------------- prep kernels ----------------
__global__ void __launch_bounds__(256)
wtrans_k(const float* __restrict__ W, float* __restrict__ WT)
{
    __shared__ float t[32][33];
    int bx = blockIdx.x * 32, by = blockIdx.y * 32;
    #pragma unroll
    for (int i = threadIdx.y; i < 32; i += 8)
        t[i][threadIdx.x] = W[(by + i) * 1024 + bx + threadIdx.x];
    __syncthreads();
    #pragma unroll
    for (int i = threadIdx.y; i < 32; i += 8)
        WT[(bx + i) * 1024 + by + threadIdx.x] = rnd32(t[threadIdx.x][i]);
}

__global__ void __launch_bounds__(256)
round_x_k(const float* __restrict__ x, float* __restrict__ o)
{
    long i = ((long)blockIdx.x * 256 + threadIdx.x) * 4;
    float4 v = *(const float4*)(x + i);
    v.x = rnd32(v.x); v.y = rnd32(v.y); v.z = rnd32(v.z); v.w = rnd32(v.w);
    *(float4*)(o + i) = v;
}

// ---------------- bind + chunk scan ----------------
__global__ void __launch_bounds__(256)
bind_scan_k(const float* __restrict__ V, const float* __restrict__ KP,
            const float* __restrict__ QP, float* __restrict__ R)
{
    const float inv = 0.03125f;  // 1/sqrt(1024)
    long idx = (long)blockIdx.x * 64 * 1024 + threadIdx.x * 4;
    float4 mr = make_float4(0.f, 0.f, 0.f, 0.f);
    float4 mi = make_float4(0.f, 0.f, 0.f, 0.f);

    #pragma unroll 4
    for (int s = 0; s < 64; s++, idx += 1024) {
        float4 v  = *(const float4*)(V + idx);
        float4 kp = *(const float4*)(KP + idx);
        float4 qp = *(const float4*)(QP + idx);
        float4 out;
        float sk, ck, sq, cq;
        __sincosf(kp.x, &sk, &ck);
        mr.x = fmaf(v.x, ck, mr.x); mi.x = fmaf(v.x, sk, mi.x);
        __sincosf(qp.x, &sq, &cq);
        out.x = (mr.x * cq + mi.x * sq) * inv;
        __sincosf(kp.y, &sk, &ck);
        mr.y = fmaf(v.y, ck, mr.y); mi.y = fmaf(v.y, sk, mi.y);
        __sincosf(qp.y, &sq, &cq);
        out.y = (mr.y * cq + mi.y * sq) * inv;
        __sincosf(kp.z, &sk, &ck);
        mr.z = fmaf(v.z, ck, mr.z); mi.z = fmaf(v.z, sk, mi.z);
        __sincosf(qp.z, &sq, &cq);
        out.z = (mr.z * cq + mi.z * sq) * inv;
        __sincosf(kp.w, &sk, &ck);
        mr.w = fmaf(v.w, ck, mr.w); mi.w = fmaf(v.w, sk, mi.w);
        __sincosf(qp.w, &sq, &cq);
        out.w = (mr.w * cq + mi.w * sq) * inv;
        *(float4*)(R + idx) = out;
    }
}

// ---------------- LayerNorm (in-place, rounds output to tf32) ----------------
__global__ void __launch_bounds__(256)
ln_k(float* __restrict__ R, const float* __restrict__ g, const float* __restrict__ b)
{
    long row = blockIdx.x;
    float4* p = (float4*)(R + row * 1024) + threadIdx.x;
    float4 v = *p;
    float s = v.x + v.y + v.z + v.w;
    float q = v.x * v.x + v.y * v.y + v.z * v.z + v.w * v.w;
    #pragma unroll
    for (int o = 16; o; o >>= 1) {
        s += __shfl_xor_sync(0xffffffffu, s, o);
        q += __shfl_xor_sync(0xffffffffu, q, o);
    }
    __shared__ float ss[8], sq2[8];
    int lane = threadIdx.x & 31, w = threadIdx.x >> 5;
    if (lane == 0) { ss[w] = s; sq2[w] = q; }
    __syncthreads();
    if (threadIdx.x == 0) {
        float S = 0.f, Q = 0.f;
        #pragma unroll
        for (int i = 0; i < 8; i++) { S += ss[i]; Q += sq2[i]; }
        ss[0] = S; sq2[0] = Q;
    }
    __syncthreads();
    float mu   = ss[0] * (1.f / 1024.f);
    float var  = sq2[0] * (1.f / 1024.f) - mu * mu;
    float rstd = rsqrtf(var + 1e-5f);
    int c = threadIdx.x * 4;
    float4 gg = *(const float4*)(g + c);
    float4 bb = *(const float4*)(b + c);
    v.x = rnd32((v.x - mu) * rstd * gg.x + bb.x);
    v.y = rnd32((v.y - mu) * rstd * gg.y + bb.y);
    v.z = rnd32((v.z - mu) * rstd * gg.z + bb.z);
    v.w = rnd32((v.w - mu) * rstd * gg.w + bb.w);
    *p = v;
}

extern "C" void kernel_launch(void* const* d_in, const int* in_sizes, int n_in,
                              void* d_out, int out_size)
{
    const float* x   = (const float*)d_in[0];
    const float* Wk  = (const float*)d_in[1];
    const float* bk  = (const float*)d_in[2];
    const float* Wv  = (const float*)d_in[3];
    const float* bv  = (const float*)d_in[4];
    const float* Wq  = (const float*)d_in[5];
    const float* bq  = (const float*)d_in[6];
    const float* Wkp = (const float*)d_in[7];
    const float* bkp = (const float*)d_in[8];
    const float* Wqp = (const float*)d_in[9];
    const float* bqp = (const float*)d_in[10];
    const float* ps  = (const float*)d_in[11];
    const float* lng = (const float*)d_in[12];
    const float* lnb = (const float*)d_in[13];
    const float* Wo  = (const float*)d_in[14];
    const float* bo  = (const float*)d_in[15];
    float* out = (float*)d_out;

    const int M = in_sizes[0] / 1024;  // 32768

    float *pK, *pV, *pQ, *pKP, *pQP, *pR, *pX, *pWT;
    cudaGetSymbolAddress((void**)&pK,  g_K);
    cudaGetSymbolAddress((void**)&pV,  g_V);
    cudaGetSymbolAddress((void**)&pQ,  g_Q);
    cudaGetSymbolAddress((void**)&pKP, g_KP);
    cudaGetSymbolAddress((void**)&pQP, g_QP);
    cudaGetSymbolAddress((void**)&pR,  g_R);
    cudaGetSymbolAddress((void**)&pX,  g_X);
    cudaGetSymbolAddress((void**)&pWT, g_WT);

    cudaFuncSetAttribute(gemm_tc<0,1>, cudaFuncAttributeMaxDynamicSharedMemorySize, SMEM_TOTAL);
    cudaFuncSetAttribute(gemm_tc<0,0>, cudaFuncAttributeMaxDynamicSharedMemorySize, SMEM_TOTAL);
    cudaFuncSetAttribute(gemm_tc<1,0>, cudaFuncAttributeMaxDynamicSharedMemorySize, SMEM_TOTAL);
    cudaFuncSetAttribute(gemm_tc<2,0>, cudaFuncAttributeMaxDynamicSharedMemorySize, SMEM_TOTAL);

    // prep: transpose+round weights, round x
    dim3 tg(32, 32), tb(32, 8);
    wtrans_k<<<tg, tb>>>(Wk,  pWT + 0 * 1048576);
    wtrans_k<<<tg, tb>>>(Wv,  pWT + 1 * 1048576);
    wtrans_k<<<tg, tb>>>(Wq,  pWT + 2 * 1048576);
    wtrans_k<<<tg, tb>>>(Wkp, pWT + 3 * 1048576);
    wtrans_k<<<tg, tb>>>(Wqp, pWT + 4 * 1048576);
    wtrans_k<<<tg, tb>>>(Wo,  pWT + 5 * 1048576);
    round_x_k<<<NELEM / 1024, 256>>>(x, pX);

    dim3 grid(N_DIM / NT, M / MT), blk(256);
    gemm_tc<0,1><<<grid, blk, SMEM_TOTAL>>>(pX, pWT + 0 * 1048576, bk, nullptr, pK);
    gemm_tc<0,0><<<grid, blk, SMEM_TOTAL>>>(pX, pWT + 1 * 1048576, bv, nullptr, pV);
    gemm_tc<0,1><<<grid, blk, SMEM_TOTAL>>>(pX, pWT + 2 * 1048576, bq, nullptr, pQ);
    gemm_tc<1,0><<<grid, blk, SMEM_TOTAL>>>(pK, pWT + 3 * 1048576, bkp, ps, pKP);
    gemm_tc<1,0><<<grid, blk, SMEM_TOTAL>>>(pQ, pWT + 4 * 1048576, bqp, ps, pQP);
    bind_scan_k<<<M / 64, 256>>>(pV, pKP, pQP, pR);
    ln_k<<<M, 256>>>(pR, lng, lnb);
    gemm_tc<2,0><<<grid, blk, SMEM_TOTAL>>>(pR, pWT + 5 * 1048576, bo, x, out);
}